// round 2
// baseline (speedup 1.0000x reference)
#include <cuda_runtime.h>
#include <cstddef>

#define N_NODES   50000
#define N_EDGES   800000
#define IN_CH     64
#define HIDDEN    128
#define NUM_GRAPHS 256

// ---------------- scratch (static device globals; no allocation) ----------------
__device__ float g_agg[(size_t)N_NODES * HIDDEN];   // aggregation buffer (used as N*64 in layer 1)
__device__ float g_h1 [(size_t)N_NODES * HIDDEN];
__device__ float g_h2 [(size_t)N_NODES * HIDDEN];
__device__ float g_sums[(size_t)NUM_GRAPHS * HIDDEN];
__device__ int   g_counts[NUM_GRAPHS];

// ---------------- vector reductions (sm_90+) ----------------
__device__ __forceinline__ void red_add_v4(float* addr, float4 v) {
    asm volatile("red.global.add.v4.f32 [%0], {%1,%2,%3,%4};"
                 :: "l"(addr), "f"(v.x), "f"(v.y), "f"(v.z), "f"(v.w) : "memory");
}
__device__ __forceinline__ void red_add_v2(float* addr, float2 v) {
    asm volatile("red.global.add.v2.f32 [%0], {%1,%2};"
                 :: "l"(addr), "f"(v.x), "f"(v.y) : "memory");
}

// ---------------- zero kernels ----------------
__global__ void zero_agg_kernel(int n4) {
    int i = blockIdx.x * blockDim.x + threadIdx.x;
    if (i < n4) reinterpret_cast<float4*>(g_agg)[i] = make_float4(0.f, 0.f, 0.f, 0.f);
}
__global__ void zero_pool_kernel() {
    int i = blockIdx.x * blockDim.x + threadIdx.x;
    if (i < NUM_GRAPHS * HIDDEN / 4)
        reinterpret_cast<float4*>(g_sums)[i] = make_float4(0.f, 0.f, 0.f, 0.f);
    if (i < NUM_GRAPHS / 4)
        reinterpret_cast<int4*>(g_counts)[i] = make_int4(0, 0, 0, 0);
}

// ---------------- edge kernel: agg[dst] += relu(x[src] + edge_attr @ We + be) ----------------
// One warp per edge. D = 64 -> 2 floats/lane, D = 128 -> 4 floats/lane.
template <int D>
__global__ void edge_kernel(const float* __restrict__ x,
                            const int* __restrict__ ei,
                            const float* __restrict__ ea,
                            const float* __restrict__ We,
                            const float* __restrict__ be) {
    __shared__ __align__(16) float Wes[8 * D];
    __shared__ __align__(16) float bes[D];
    for (int i = threadIdx.x; i < 8 * D; i += blockDim.x) Wes[i] = We[i];
    for (int i = threadIdx.x; i < D; i += blockDim.x)     bes[i] = be[i];
    __syncthreads();

    const int lane = threadIdx.x & 31;
    const int warp = (blockIdx.x * blockDim.x + threadIdx.x) >> 5;
    const int nwarps = (gridDim.x * blockDim.x) >> 5;
    const int* __restrict__ srcp = ei;
    const int* __restrict__ dstp = ei + N_EDGES;

    if constexpr (D == 128) {
        const float4* Wes4 = reinterpret_cast<const float4*>(Wes);
        const float4  bj   = reinterpret_cast<const float4*>(bes)[lane];
        for (int e = warp; e < N_EDGES; e += nwarps) {
            const int s = srcp[e];
            const int d = dstp[e];
            const float4* eav = reinterpret_cast<const float4*>(ea + (size_t)e * 8);
            float4 a0 = eav[0], a1 = eav[1];
            float ak[8] = {a0.x, a0.y, a0.z, a0.w, a1.x, a1.y, a1.z, a1.w};
            float4 acc = bj;
#pragma unroll
            for (int k = 0; k < 8; k++) {
                float4 wv = Wes4[k * 32 + lane];
                acc.x = fmaf(ak[k], wv.x, acc.x);
                acc.y = fmaf(ak[k], wv.y, acc.y);
                acc.z = fmaf(ak[k], wv.z, acc.z);
                acc.w = fmaf(ak[k], wv.w, acc.w);
            }
            float4 xv = reinterpret_cast<const float4*>(x + (size_t)s * D)[lane];
            float4 m;
            m.x = fmaxf(xv.x + acc.x, 0.f);
            m.y = fmaxf(xv.y + acc.y, 0.f);
            m.z = fmaxf(xv.z + acc.z, 0.f);
            m.w = fmaxf(xv.w + acc.w, 0.f);
            red_add_v4(&g_agg[(size_t)d * D + lane * 4], m);
        }
    } else { // D == 64
        const float2* Wes2 = reinterpret_cast<const float2*>(Wes);
        const float2  bj   = reinterpret_cast<const float2*>(bes)[lane];
        for (int e = warp; e < N_EDGES; e += nwarps) {
            const int s = srcp[e];
            const int d = dstp[e];
            const float4* eav = reinterpret_cast<const float4*>(ea + (size_t)e * 8);
            float4 a0 = eav[0], a1 = eav[1];
            float ak[8] = {a0.x, a0.y, a0.z, a0.w, a1.x, a1.y, a1.z, a1.w};
            float2 acc = bj;
#pragma unroll
            for (int k = 0; k < 8; k++) {
                float2 wv = Wes2[k * 32 + lane];
                acc.x = fmaf(ak[k], wv.x, acc.x);
                acc.y = fmaf(ak[k], wv.y, acc.y);
            }
            float2 xv = reinterpret_cast<const float2*>(x + (size_t)s * D)[lane];
            float2 m;
            m.x = fmaxf(xv.x + acc.x, 0.f);
            m.y = fmaxf(xv.y + acc.y, 0.f);
            red_add_v2(&g_agg[(size_t)d * D + lane * 2], m);
        }
    }
}

// ---------------- node kernel: out = relu((x + agg) @ W + b), optional fused mean-pool accum ----------------
// 256 threads, 64 nodes per block. Each thread: 8 nodes x 4 output channels.
template <int K, bool POOL>
__global__ void node_kernel(const float* __restrict__ x,
                            const float* __restrict__ W,
                            const float* __restrict__ b,
                            const int* __restrict__ batch,
                            float* __restrict__ out) {
    extern __shared__ __align__(16) float sm[];
    float* Ws  = sm;               // K * 128
    float* ins = sm + K * 128;     // 64 * K
    const int tid = threadIdx.x;
    constexpr int K4 = K / 4;

    const float4* W4 = reinterpret_cast<const float4*>(W);
    float4* Ws4 = reinterpret_cast<float4*>(Ws);
    for (int i = tid; i < K * 32; i += 256) Ws4[i] = W4[i];

    const int base = blockIdx.x * 64;
    const float4* x4 = reinterpret_cast<const float4*>(x);
    const float4* a4 = reinterpret_cast<const float4*>(g_agg);
    float4* in4 = reinterpret_cast<float4*>(ins);
    for (int i = tid; i < 64 * K4; i += 256) {
        const int r = i / K4, c = i % K4;
        const int n = base + r;
        float4 v = make_float4(0.f, 0.f, 0.f, 0.f);
        if (n < N_NODES) {
            float4 xv = x4[(size_t)n * K4 + c];
            float4 av = a4[(size_t)n * K4 + c];
            v = make_float4(xv.x + av.x, xv.y + av.y, xv.z + av.z, xv.w + av.w);
        }
        in4[i] = v;
    }
    __syncthreads();

    const int w = tid >> 5, lane = tid & 31;
    const float4 bj = reinterpret_cast<const float4*>(b)[lane];
    float4 acc[8];
#pragma unroll
    for (int m = 0; m < 8; m++) acc[m] = bj;

    const float* inrow = ins + (w * 8) * K;
#pragma unroll 2
    for (int k = 0; k < K; k++) {
        const float4 wv = Ws4[k * 32 + lane];
#pragma unroll
        for (int m = 0; m < 8; m++) {
            const float iv = inrow[m * K + k];
            acc[m].x = fmaf(iv, wv.x, acc[m].x);
            acc[m].y = fmaf(iv, wv.y, acc[m].y);
            acc[m].z = fmaf(iv, wv.z, acc[m].z);
            acc[m].w = fmaf(iv, wv.w, acc[m].w);
        }
    }

#pragma unroll
    for (int m = 0; m < 8; m++) {
        const int n = base + w * 8 + m;
        if (n < N_NODES) {
            float4 r;
            r.x = fmaxf(acc[m].x, 0.f);
            r.y = fmaxf(acc[m].y, 0.f);
            r.z = fmaxf(acc[m].z, 0.f);
            r.w = fmaxf(acc[m].w, 0.f);
            if (POOL) {
                const int g = batch[n];
                red_add_v4(&g_sums[(size_t)g * HIDDEN + lane * 4], r);
            } else {
                reinterpret_cast<float4*>(out)[(size_t)n * 32 + lane] = r;
            }
        }
    }
}

// ---------------- per-graph node counts (smem histogram) ----------------
__global__ void count_kernel(const int* __restrict__ batch) {
    __shared__ int hist[NUM_GRAPHS];
    for (int i = threadIdx.x; i < NUM_GRAPHS; i += blockDim.x) hist[i] = 0;
    __syncthreads();
    for (int n = blockIdx.x * blockDim.x + threadIdx.x; n < N_NODES; n += gridDim.x * blockDim.x)
        atomicAdd(&hist[batch[n]], 1);
    __syncthreads();
    for (int i = threadIdx.x; i < NUM_GRAPHS; i += blockDim.x)
        if (hist[i]) atomicAdd(&g_counts[i], hist[i]);
}

// ---------------- final divide ----------------
__global__ void div_kernel(float* __restrict__ out) {
    const int g = blockIdx.x;
    const int j = threadIdx.x;
    const float c = fmaxf((float)g_counts[g], 1.0f);
    out[g * HIDDEN + j] = g_sums[g * HIDDEN + j] / c;
}

// ---------------- device-symbol address helpers (host API only; capture-safe) ----------------
static float* h1_ptr() {
    void* p = nullptr;
    cudaGetSymbolAddress(&p, g_h1);
    return (float*)p;
}
static float* h2_ptr() {
    void* p = nullptr;
    cudaGetSymbolAddress(&p, g_h2);
    return (float*)p;
}

// ---------------- launch ----------------
extern "C" void kernel_launch(void* const* d_in, const int* in_sizes, int n_in,
                              void* d_out, int out_size) {
    const float* x     = (const float*)d_in[0];
    const int*   ei    = (const int*)d_in[1];     // int32 (JAX default x64-disabled)
    const float* ea    = (const float*)d_in[2];
    const int*   batch = (const int*)d_in[3];     // int32
    const float *W1 = (const float*)d_in[4],  *b1 = (const float*)d_in[5];
    const float *We1= (const float*)d_in[6],  *be1= (const float*)d_in[7];
    const float *W2 = (const float*)d_in[8],  *b2 = (const float*)d_in[9];
    const float *We2= (const float*)d_in[10], *be2= (const float*)d_in[11];
    const float *W3 = (const float*)d_in[12], *b3 = (const float*)d_in[13];
    const float *We3= (const float*)d_in[14], *be3= (const float*)d_in[15];
    float* out = (float*)d_out;

    float* h1 = h1_ptr();
    float* h2 = h2_ptr();

    const int smem64  = (64  * 128 + 64 * 64)  * 4;  // 48 KB
    const int smem128 = (128 * 128 + 64 * 128) * 4;  // 96 KB
    cudaFuncSetAttribute(node_kernel<64,  false>, cudaFuncAttributeMaxDynamicSharedMemorySize, smem64);
    cudaFuncSetAttribute(node_kernel<128, false>, cudaFuncAttributeMaxDynamicSharedMemorySize, smem128);
    cudaFuncSetAttribute(node_kernel<128, true >, cudaFuncAttributeMaxDynamicSharedMemorySize, smem128);

    const int EDGE_GRID = 152 * 8;
    const int NODE_GRID = (N_NODES + 63) / 64;

    // ---- layer 1 (64 -> 128) ----
    {
        const int n4 = N_NODES * IN_CH / 4;
        zero_agg_kernel<<<(n4 + 255) / 256, 256>>>(n4);
        edge_kernel<64><<<EDGE_GRID, 256>>>(x, ei, ea, We1, be1);
        node_kernel<64, false><<<NODE_GRID, 256, smem64>>>(x, W1, b1, nullptr, h1);
    }
    // ---- layer 2 (128 -> 128) ----
    {
        const int n4 = N_NODES * HIDDEN / 4;
        zero_agg_kernel<<<(n4 + 255) / 256, 256>>>(n4);
        edge_kernel<128><<<EDGE_GRID, 256>>>(h1, ei, ea, We2, be2);
        node_kernel<128, false><<<NODE_GRID, 256, smem128>>>(h1, W2, b2, nullptr, h2);
    }
    // ---- layer 3 (128 -> 128) + fused pool ----
    {
        const int n4 = N_NODES * HIDDEN / 4;
        zero_agg_kernel<<<(n4 + 255) / 256, 256>>>(n4);
        zero_pool_kernel<<<32, 256>>>();
        edge_kernel<128><<<EDGE_GRID, 256>>>(h2, ei, ea, We3, be3);
        count_kernel<<<128, 256>>>(batch);
        node_kernel<128, true><<<NODE_GRID, 256, smem128>>>(h2, W3, b3, batch, nullptr);
        div_kernel<<<NUM_GRAPHS, HIDDEN>>>(out);
    }
}

// round 4
// speedup vs baseline: 1.2040x; 1.2040x over previous
#include <cuda_runtime.h>
#include <cstddef>

#define N_NODES   50000
#define N_EDGES   800000
#define IN_CH     64
#define HIDDEN    128
#define NUM_GRAPHS 256

// ---------------- scratch (static device globals; no allocation) ----------------
__device__ float g_agg1[(size_t)N_NODES * IN_CH];    // layer-1 aggregation (64 ch)
__device__ float g_agg2[(size_t)N_NODES * HIDDEN];   // layer-2 aggregation
__device__ float g_agg3[(size_t)N_NODES * HIDDEN];   // layer-3 aggregation
__device__ float g_h1 [(size_t)N_NODES * HIDDEN];
__device__ float g_h2 [(size_t)N_NODES * HIDDEN];
__device__ float g_sums[(size_t)NUM_GRAPHS * HIDDEN];
__device__ int   g_counts[NUM_GRAPHS];

// ---------------- vector reductions (sm_90+) ----------------
__device__ __forceinline__ void red_add_v4(float* addr, float4 v) {
    asm volatile("red.global.add.v4.f32 [%0], {%1,%2,%3,%4};"
                 :: "l"(addr), "f"(v.x), "f"(v.y), "f"(v.z), "f"(v.w) : "memory");
}
__device__ __forceinline__ void red_add_v2(float* addr, float2 v) {
    asm volatile("red.global.add.v2.f32 [%0], {%1,%2};"
                 :: "l"(addr), "f"(v.x), "f"(v.y) : "memory");
}

// ---------------- zero kernels ----------------
__global__ void zero_a_kernel() {  // agg1 (64ch)
    const int n4 = N_NODES * IN_CH / 4;
    for (int i = blockIdx.x * blockDim.x + threadIdx.x; i < n4; i += gridDim.x * blockDim.x)
        reinterpret_cast<float4*>(g_agg1)[i] = make_float4(0.f, 0.f, 0.f, 0.f);
}
__global__ void zero_b_kernel() {  // agg2 + agg3
    const int n4 = N_NODES * HIDDEN / 4;
    for (int i = blockIdx.x * blockDim.x + threadIdx.x; i < n4; i += gridDim.x * blockDim.x) {
        reinterpret_cast<float4*>(g_agg2)[i] = make_float4(0.f, 0.f, 0.f, 0.f);
        reinterpret_cast<float4*>(g_agg3)[i] = make_float4(0.f, 0.f, 0.f, 0.f);
    }
}
__global__ void zero_pool_kernel() {
    int i = blockIdx.x * blockDim.x + threadIdx.x;
    if (i < NUM_GRAPHS * HIDDEN / 4)
        reinterpret_cast<float4*>(g_sums)[i] = make_float4(0.f, 0.f, 0.f, 0.f);
    if (i < NUM_GRAPHS / 4)
        reinterpret_cast<int4*>(g_counts)[i] = make_int4(0, 0, 0, 0);
}

// ---------------- edge kernel: agg[dst] += relu(x[src] + edge_attr @ We + be) ----------------
// One warp per edge; contiguous per-warp edge chunks; next-edge prefetch pipeline.
template <int D>
__global__ void edge_kernel(const float* __restrict__ x,
                            const int* __restrict__ ei,
                            const float* __restrict__ ea,
                            const float* __restrict__ We,
                            const float* __restrict__ be,
                            float* __restrict__ agg) {
    __shared__ __align__(16) float Wes[8 * D];
    __shared__ __align__(16) float bes[D];
    for (int i = threadIdx.x; i < 8 * D; i += blockDim.x) Wes[i] = We[i];
    for (int i = threadIdx.x; i < D; i += blockDim.x)     bes[i] = be[i];
    __syncthreads();

    const int lane = threadIdx.x & 31;
    const int wid  = (blockIdx.x * blockDim.x + threadIdx.x) >> 5;
    const int nw   = (gridDim.x * blockDim.x) >> 5;
    const int per  = (N_EDGES + nw - 1) / nw;
    const int e0   = wid * per;
    const int e1   = (e0 + per < N_EDGES) ? (e0 + per) : N_EDGES;
    if (e0 >= e1) return;

    const int* __restrict__ srcp = ei;
    const int* __restrict__ dstp = ei + N_EDGES;

    if constexpr (D == 128) {
        const float4* Wes4 = reinterpret_cast<const float4*>(Wes);
        const float4  bj   = reinterpret_cast<const float4*>(bes)[lane];

        int s = srcp[e0], d = dstp[e0];
        const float4* eav = reinterpret_cast<const float4*>(ea + (size_t)e0 * 8);
        float4 a0 = eav[0], a1 = eav[1];

        for (int e = e0; e < e1; ++e) {
            // issue the gather for the current edge as early as possible
            float4 xv = reinterpret_cast<const float4*>(x + (size_t)s * D)[lane];

            // prefetch next edge's metadata
            int sn = 0, dn = 0;
            float4 a0n = make_float4(0, 0, 0, 0), a1n = a0n;
            if (e + 1 < e1) {
                sn = srcp[e + 1];
                dn = dstp[e + 1];
                const float4* eavn = reinterpret_cast<const float4*>(ea + (size_t)(e + 1) * 8);
                a0n = eavn[0];
                a1n = eavn[1];
            }

            float ak[8] = {a0.x, a0.y, a0.z, a0.w, a1.x, a1.y, a1.z, a1.w};
            float4 acc = bj;
#pragma unroll
            for (int k = 0; k < 8; k++) {
                float4 wv = Wes4[k * 32 + lane];
                acc.x = fmaf(ak[k], wv.x, acc.x);
                acc.y = fmaf(ak[k], wv.y, acc.y);
                acc.z = fmaf(ak[k], wv.z, acc.z);
                acc.w = fmaf(ak[k], wv.w, acc.w);
            }
            float4 m;
            m.x = fmaxf(xv.x + acc.x, 0.f);
            m.y = fmaxf(xv.y + acc.y, 0.f);
            m.z = fmaxf(xv.z + acc.z, 0.f);
            m.w = fmaxf(xv.w + acc.w, 0.f);
            red_add_v4(&agg[(size_t)d * D + lane * 4], m);

            s = sn; d = dn; a0 = a0n; a1 = a1n;
        }
    } else { // D == 64
        const float2* Wes2 = reinterpret_cast<const float2*>(Wes);
        const float2  bj   = reinterpret_cast<const float2*>(bes)[lane];

        int s = srcp[e0], d = dstp[e0];
        const float4* eav = reinterpret_cast<const float4*>(ea + (size_t)e0 * 8);
        float4 a0 = eav[0], a1 = eav[1];

        for (int e = e0; e < e1; ++e) {
            float2 xv = reinterpret_cast<const float2*>(x + (size_t)s * D)[lane];

            int sn = 0, dn = 0;
            float4 a0n = make_float4(0, 0, 0, 0), a1n = a0n;
            if (e + 1 < e1) {
                sn = srcp[e + 1];
                dn = dstp[e + 1];
                const float4* eavn = reinterpret_cast<const float4*>(ea + (size_t)(e + 1) * 8);
                a0n = eavn[0];
                a1n = eavn[1];
            }

            float ak[8] = {a0.x, a0.y, a0.z, a0.w, a1.x, a1.y, a1.z, a1.w};
            float2 acc = bj;
#pragma unroll
            for (int k = 0; k < 8; k++) {
                float2 wv = Wes2[k * 32 + lane];
                acc.x = fmaf(ak[k], wv.x, acc.x);
                acc.y = fmaf(ak[k], wv.y, acc.y);
            }
            float2 m;
            m.x = fmaxf(xv.x + acc.x, 0.f);
            m.y = fmaxf(xv.y + acc.y, 0.f);
            red_add_v2(&agg[(size_t)d * D + lane * 2], m);

            s = sn; d = dn; a0 = a0n; a1 = a1n;
        }
    }
}

// ---------------- node kernel: out = relu((x + agg) @ W + b), optional fused mean-pool accum ----------------
// 256 threads, 64 nodes/block. Each thread: 8 nodes x 4 output channels. k unrolled by 4.
template <int K, bool POOL>
__global__ void node_kernel(const float* __restrict__ x,
                            const float* __restrict__ agg,
                            const float* __restrict__ W,
                            const float* __restrict__ b,
                            const int* __restrict__ batch,
                            float* __restrict__ out) {
    extern __shared__ __align__(16) float sm[];
    float* Ws  = sm;               // K * 128
    float* ins = sm + K * 128;     // 64 * K
    const int tid = threadIdx.x;
    constexpr int K4 = K / 4;

    const float4* W4 = reinterpret_cast<const float4*>(W);
    float4* Ws4 = reinterpret_cast<float4*>(Ws);
    for (int i = tid; i < K * 32; i += 256) Ws4[i] = W4[i];

    const int base = blockIdx.x * 64;
    const float4* x4 = reinterpret_cast<const float4*>(x);
    const float4* a4 = reinterpret_cast<const float4*>(agg);
    float4* in4 = reinterpret_cast<float4*>(ins);
    for (int i = tid; i < 64 * K4; i += 256) {
        const int r = i / K4, c = i % K4;
        const int n = base + r;
        float4 v = make_float4(0.f, 0.f, 0.f, 0.f);
        if (n < N_NODES) {
            float4 xv = x4[(size_t)n * K4 + c];
            float4 av = a4[(size_t)n * K4 + c];
            v = make_float4(xv.x + av.x, xv.y + av.y, xv.z + av.z, xv.w + av.w);
        }
        in4[i] = v;
    }
    __syncthreads();

    const int w = tid >> 5, lane = tid & 31;
    const float4 bj = reinterpret_cast<const float4*>(b)[lane];
    float4 acc[8];
#pragma unroll
    for (int m = 0; m < 8; m++) acc[m] = bj;

    const float* inrow = ins + (w * 8) * K;
#pragma unroll 1
    for (int k = 0; k < K; k += 4) {
        const float4 wv0 = Ws4[(k + 0) * 32 + lane];
        const float4 wv1 = Ws4[(k + 1) * 32 + lane];
        const float4 wv2 = Ws4[(k + 2) * 32 + lane];
        const float4 wv3 = Ws4[(k + 3) * 32 + lane];
#pragma unroll
        for (int m = 0; m < 8; m++) {
            const float4 iv = *reinterpret_cast<const float4*>(inrow + m * K + k);
            acc[m].x = fmaf(iv.x, wv0.x, acc[m].x);
            acc[m].y = fmaf(iv.x, wv0.y, acc[m].y);
            acc[m].z = fmaf(iv.x, wv0.z, acc[m].z);
            acc[m].w = fmaf(iv.x, wv0.w, acc[m].w);
            acc[m].x = fmaf(iv.y, wv1.x, acc[m].x);
            acc[m].y = fmaf(iv.y, wv1.y, acc[m].y);
            acc[m].z = fmaf(iv.y, wv1.z, acc[m].z);
            acc[m].w = fmaf(iv.y, wv1.w, acc[m].w);
            acc[m].x = fmaf(iv.z, wv2.x, acc[m].x);
            acc[m].y = fmaf(iv.z, wv2.y, acc[m].y);
            acc[m].z = fmaf(iv.z, wv2.z, acc[m].z);
            acc[m].w = fmaf(iv.z, wv2.w, acc[m].w);
            acc[m].x = fmaf(iv.w, wv3.x, acc[m].x);
            acc[m].y = fmaf(iv.w, wv3.y, acc[m].y);
            acc[m].z = fmaf(iv.w, wv3.z, acc[m].z);
            acc[m].w = fmaf(iv.w, wv3.w, acc[m].w);
        }
    }

#pragma unroll
    for (int m = 0; m < 8; m++) {
        const int n = base + w * 8 + m;
        if (n < N_NODES) {
            float4 r;
            r.x = fmaxf(acc[m].x, 0.f);
            r.y = fmaxf(acc[m].y, 0.f);
            r.z = fmaxf(acc[m].z, 0.f);
            r.w = fmaxf(acc[m].w, 0.f);
            if (POOL) {
                const int g = batch[n];
                red_add_v4(&g_sums[(size_t)g * HIDDEN + lane * 4], r);
            } else {
                reinterpret_cast<float4*>(out)[(size_t)n * 32 + lane] = r;
            }
        }
    }
}

// ---------------- per-graph node counts (smem histogram) ----------------
__global__ void count_kernel(const int* __restrict__ batch) {
    __shared__ int hist[NUM_GRAPHS];
    for (int i = threadIdx.x; i < NUM_GRAPHS; i += blockDim.x) hist[i] = 0;
    __syncthreads();
    for (int n = blockIdx.x * blockDim.x + threadIdx.x; n < N_NODES; n += gridDim.x * blockDim.x)
        atomicAdd(&hist[batch[n]], 1);
    __syncthreads();
    for (int i = threadIdx.x; i < NUM_GRAPHS; i += blockDim.x)
        if (hist[i]) atomicAdd(&g_counts[i], hist[i]);
}

// ---------------- final divide ----------------
__global__ void div_kernel(float* __restrict__ out) {
    const int g = blockIdx.x;
    const int j = threadIdx.x;
    const float c = fmaxf((float)g_counts[g], 1.0f);
    out[g * HIDDEN + j] = g_sums[g * HIDDEN + j] / c;
}

// ---------------- device-symbol address helpers (host API only; capture-safe) ----------------
template <typename T>
static T* sym_addr(T& sym) {
    void* p = nullptr;
    cudaGetSymbolAddress(&p, sym);
    return (T*)p;
}

// ---------------- launch ----------------
extern "C" void kernel_launch(void* const* d_in, const int* in_sizes, int n_in,
                              void* d_out, int out_size) {
    const float* x     = (const float*)d_in[0];
    const int*   ei    = (const int*)d_in[1];     // int32 (JAX default x64-disabled)
    const float* ea    = (const float*)d_in[2];
    const int*   batch = (const int*)d_in[3];     // int32
    const float *W1 = (const float*)d_in[4],  *b1 = (const float*)d_in[5];
    const float *We1= (const float*)d_in[6],  *be1= (const float*)d_in[7];
    const float *W2 = (const float*)d_in[8],  *b2 = (const float*)d_in[9];
    const float *We2= (const float*)d_in[10], *be2= (const float*)d_in[11];
    const float *W3 = (const float*)d_in[12], *b3 = (const float*)d_in[13];
    const float *We3= (const float*)d_in[14], *be3= (const float*)d_in[15];
    float* out = (float*)d_out;

    float* agg1 = sym_addr(*g_agg1);
    float* agg2 = sym_addr(*g_agg2);
    float* agg3 = sym_addr(*g_agg3);
    float* h1   = sym_addr(*g_h1);
    float* h2   = sym_addr(*g_h2);

    const int smem64  = (64  * 128 + 64 * 64)  * 4;  // 48 KB
    const int smem128 = (128 * 128 + 64 * 128) * 4;  // 96 KB
    cudaFuncSetAttribute(node_kernel<64,  false>, cudaFuncAttributeMaxDynamicSharedMemorySize, smem64);
    cudaFuncSetAttribute(node_kernel<128, false>, cudaFuncAttributeMaxDynamicSharedMemorySize, smem128);
    cudaFuncSetAttribute(node_kernel<128, true >, cudaFuncAttributeMaxDynamicSharedMemorySize, smem128);

    const int EDGE_GRID = 152 * 8;
    const int NODE_GRID = (N_NODES + 63) / 64;

    // zero_pool MUST precede count_kernel (it zeroes g_counts).
    zero_a_kernel<<<1024, 256>>>();                                                    // 1
    zero_b_kernel<<<2048, 256>>>();                                                    // 2
    zero_pool_kernel<<<32, 256>>>();                                                   // 3
    edge_kernel<64><<<EDGE_GRID, 256>>>(x, ei, ea, We1, be1, agg1);                    // 4
    node_kernel<64, false><<<NODE_GRID, 256, smem64>>>(x, agg1, W1, b1, nullptr, h1);  // 5
    count_kernel<<<128, 256>>>(batch);                                                 // 6
    edge_kernel<128><<<EDGE_GRID, 256>>>(h1, ei, ea, We2, be2, agg2);                  // 7
    node_kernel<128, false><<<NODE_GRID, 256, smem128>>>(h1, agg2, W2, b2, nullptr, h2); // 8
    edge_kernel<128><<<EDGE_GRID, 256>>>(h2, ei, ea, We3, be3, agg3);                  // 9
    node_kernel<128, true><<<NODE_GRID, 256, smem128>>>(h2, agg3, W3, b3, batch, nullptr); // 10
    div_kernel<<<NUM_GRAPHS, HIDDEN>>>(out);                                           // 11
}

// round 5
// speedup vs baseline: 1.5336x; 1.2738x over previous
#include <cuda_runtime.h>
#include <cstddef>

#define N_NODES   50000
#define N_EDGES   800000
#define IN_CH     64
#define HIDDEN    128
#define NUM_GRAPHS 256

typedef unsigned long long u64;

// ---------------- scratch (static device globals; no allocation) ----------------
__device__ float g_agg1[(size_t)N_NODES * IN_CH];
__device__ float g_agg2[(size_t)N_NODES * HIDDEN];
__device__ float g_agg3[(size_t)N_NODES * HIDDEN];
__device__ float g_h1 [(size_t)N_NODES * HIDDEN];
__device__ float g_h2 [(size_t)N_NODES * HIDDEN];
__device__ float g_sums[(size_t)NUM_GRAPHS * HIDDEN];
__device__ int   g_counts[NUM_GRAPHS];

// ---------------- packed f32x2 helpers (sm_103a FFMA2) ----------------
__device__ __forceinline__ u64 pack2(float lo, float hi) {
    u64 r;
    asm("mov.b64 %0, {%1, %2};" : "=l"(r) : "r"(__float_as_uint(lo)), "r"(__float_as_uint(hi)));
    return r;
}
__device__ __forceinline__ u64 fma2(u64 a, u64 b, u64 c) {
    u64 d;
    asm("fma.rn.f32x2 %0, %1, %2, %3;" : "=l"(d) : "l"(a), "l"(b), "l"(c));
    return d;
}
__device__ __forceinline__ float2 unpack2(u64 v) {
    unsigned lo, hi;
    asm("mov.b64 {%0, %1}, %2;" : "=r"(lo), "=r"(hi) : "l"(v));
    return make_float2(__uint_as_float(lo), __uint_as_float(hi));
}

// ---------------- vector reductions (sm_90+) ----------------
__device__ __forceinline__ void red_add_v4(float* addr, float4 v) {
    asm volatile("red.global.add.v4.f32 [%0], {%1,%2,%3,%4};"
                 :: "l"(addr), "f"(v.x), "f"(v.y), "f"(v.z), "f"(v.w) : "memory");
}

// ---------------- zero kernels ----------------
__global__ void zero_a_kernel() {
    const int n4 = N_NODES * IN_CH / 4;
    for (int i = blockIdx.x * blockDim.x + threadIdx.x; i < n4; i += gridDim.x * blockDim.x)
        reinterpret_cast<float4*>(g_agg1)[i] = make_float4(0.f, 0.f, 0.f, 0.f);
}
__global__ void zero_b_kernel() {
    const int n4 = N_NODES * HIDDEN / 4;
    for (int i = blockIdx.x * blockDim.x + threadIdx.x; i < n4; i += gridDim.x * blockDim.x) {
        reinterpret_cast<float4*>(g_agg2)[i] = make_float4(0.f, 0.f, 0.f, 0.f);
        reinterpret_cast<float4*>(g_agg3)[i] = make_float4(0.f, 0.f, 0.f, 0.f);
    }
}
__global__ void zero_pool_kernel() {
    int i = blockIdx.x * blockDim.x + threadIdx.x;
    if (i < NUM_GRAPHS * HIDDEN / 4)
        reinterpret_cast<float4*>(g_sums)[i] = make_float4(0.f, 0.f, 0.f, 0.f);
    if (i < NUM_GRAPHS / 4)
        reinterpret_cast<int4*>(g_counts)[i] = make_int4(0, 0, 0, 0);
}

// ---------------- edge kernel D=64: two edges per warp, weights in registers ----------------
__global__ void edge_kernel64(const float* __restrict__ x,
                              const int* __restrict__ ei,
                              const float* __restrict__ ea,
                              const float* __restrict__ We,
                              const float* __restrict__ be,
                              float* __restrict__ agg) {
    __shared__ __align__(16) float4 Wes4[8 * 16];   // [k][sub]  (We is [8][64])
    __shared__ __align__(16) float4 bes4[16];
    for (int i = threadIdx.x; i < 8 * 16; i += blockDim.x)
        Wes4[i] = reinterpret_cast<const float4*>(We)[i];
    if (threadIdx.x < 16) bes4[threadIdx.x] = reinterpret_cast<const float4*>(be)[threadIdx.x];
    __syncthreads();

    const int lane = threadIdx.x & 31;
    const int half = lane >> 4;        // which of the 2 edges this lane serves
    const int sub  = lane & 15;        // channel group: sub*4 .. sub*4+3
    float4 w[8];
#pragma unroll
    for (int k = 0; k < 8; k++) w[k] = Wes4[k * 16 + sub];
    const float4 bj = bes4[sub];

    const int wid = (blockIdx.x * blockDim.x + threadIdx.x) >> 5;
    const int nw  = (gridDim.x * blockDim.x) >> 5;
    int per = (N_EDGES + nw - 1) / nw;
    per = (per + 1) & ~1;                       // even so pairs don't split
    const int e0 = wid * per;
    const int e1 = (e0 + per < N_EDGES) ? (e0 + per) : N_EDGES;
    if (e0 >= e1) return;

    const int* __restrict__ srcp = ei;
    const int* __restrict__ dstp = ei + N_EDGES;
    const float4* __restrict__ eav = reinterpret_cast<const float4*>(ea);

    // preload edge e0+half (clamped)
    int my = e0 + half;
    int idx = (my < e1) ? my : (e1 - 1);
    int s = srcp[idx], d = dstp[idx];
    float4 a0 = eav[(size_t)idx * 2], a1 = eav[(size_t)idx * 2 + 1];

    for (int e = e0; e < e1; e += 2) {
        // gather for current edge early
        float4 xv = reinterpret_cast<const float4*>(x + (size_t)s * 64)[sub];

        // prefetch next pair's metadata
        int sn = s, dn = d;
        float4 a0n = a0, a1n = a1;
        if (e + 2 < e1) {
            int myn = e + 2 + half;
            int idxn = (myn < e1) ? myn : (e1 - 1);
            sn = srcp[idxn]; dn = dstp[idxn];
            a0n = eav[(size_t)idxn * 2]; a1n = eav[(size_t)idxn * 2 + 1];
        }

        float ak[8] = {a0.x, a0.y, a0.z, a0.w, a1.x, a1.y, a1.z, a1.w};
        float4 acc = bj;
#pragma unroll
        for (int k = 0; k < 8; k++) {
            acc.x = fmaf(ak[k], w[k].x, acc.x);
            acc.y = fmaf(ak[k], w[k].y, acc.y);
            acc.z = fmaf(ak[k], w[k].z, acc.z);
            acc.w = fmaf(ak[k], w[k].w, acc.w);
        }
        float4 m;
        m.x = fmaxf(xv.x + acc.x, 0.f);
        m.y = fmaxf(xv.y + acc.y, 0.f);
        m.z = fmaxf(xv.z + acc.z, 0.f);
        m.w = fmaxf(xv.w + acc.w, 0.f);
        if (e + half < e1)
            red_add_v4(&agg[(size_t)d * 64 + sub * 4], m);

        s = sn; d = dn; a0 = a0n; a1 = a1n;
    }
}

// ---------------- edge kernel D=128: one edge per warp, weights in registers ----------------
__global__ void edge_kernel128(const float* __restrict__ x,
                               const int* __restrict__ ei,
                               const float* __restrict__ ea,
                               const float* __restrict__ We,
                               const float* __restrict__ be,
                               float* __restrict__ agg) {
    __shared__ __align__(16) float4 Wes4[8 * 32];   // [k][lane]  (We is [8][128])
    __shared__ __align__(16) float4 bes4[32];
    for (int i = threadIdx.x; i < 8 * 32; i += blockDim.x)
        Wes4[i] = reinterpret_cast<const float4*>(We)[i];
    if (threadIdx.x < 32) bes4[threadIdx.x] = reinterpret_cast<const float4*>(be)[threadIdx.x];
    __syncthreads();

    const int lane = threadIdx.x & 31;
    float4 w[8];
#pragma unroll
    for (int k = 0; k < 8; k++) w[k] = Wes4[k * 32 + lane];
    const float4 bj = bes4[lane];

    const int wid = (blockIdx.x * blockDim.x + threadIdx.x) >> 5;
    const int nw  = (gridDim.x * blockDim.x) >> 5;
    const int per = (N_EDGES + nw - 1) / nw;
    const int e0  = wid * per;
    const int e1  = (e0 + per < N_EDGES) ? (e0 + per) : N_EDGES;
    if (e0 >= e1) return;

    const int* __restrict__ srcp = ei;
    const int* __restrict__ dstp = ei + N_EDGES;
    const float4* __restrict__ eav = reinterpret_cast<const float4*>(ea);

    int s = srcp[e0], d = dstp[e0];
    float4 a0 = eav[(size_t)e0 * 2], a1 = eav[(size_t)e0 * 2 + 1];

    for (int e = e0; e < e1; ++e) {
        float4 xv = reinterpret_cast<const float4*>(x + (size_t)s * 128)[lane];

        int sn = s, dn = d;
        float4 a0n = a0, a1n = a1;
        if (e + 1 < e1) {
            sn = srcp[e + 1]; dn = dstp[e + 1];
            a0n = eav[(size_t)(e + 1) * 2]; a1n = eav[(size_t)(e + 1) * 2 + 1];
        }

        float ak[8] = {a0.x, a0.y, a0.z, a0.w, a1.x, a1.y, a1.z, a1.w};
        float4 acc = bj;
#pragma unroll
        for (int k = 0; k < 8; k++) {
            acc.x = fmaf(ak[k], w[k].x, acc.x);
            acc.y = fmaf(ak[k], w[k].y, acc.y);
            acc.z = fmaf(ak[k], w[k].z, acc.z);
            acc.w = fmaf(ak[k], w[k].w, acc.w);
        }
        float4 m;
        m.x = fmaxf(xv.x + acc.x, 0.f);
        m.y = fmaxf(xv.y + acc.y, 0.f);
        m.z = fmaxf(xv.z + acc.z, 0.f);
        m.w = fmaxf(xv.w + acc.w, 0.f);
        red_add_v4(&agg[(size_t)d * 128 + lane * 4], m);

        s = sn; d = dn; a0 = a0n; a1 = a1n;
    }
}

// ---------------- node kernel: out = relu((x + agg) @ W + b), FFMA2 inner loop ----------------
// 256 threads, 64 nodes/block. Each thread: 8 nodes x 4 output channels.
template <int K, bool POOL>
__global__ void node_kernel(const float* __restrict__ x,
                            const float* __restrict__ agg,
                            const float* __restrict__ W,
                            const float* __restrict__ b,
                            const int* __restrict__ batch,
                            float* __restrict__ out) {
    extern __shared__ __align__(16) float sm[];
    float* Ws  = sm;               // K * 128
    float* ins = sm + K * 128;     // 64 * K
    const int tid = threadIdx.x;
    constexpr int K4 = K / 4;

    const float4* W4 = reinterpret_cast<const float4*>(W);
    float4* Ws4 = reinterpret_cast<float4*>(Ws);
    for (int i = tid; i < K * 32; i += 256) Ws4[i] = W4[i];

    const int base = blockIdx.x * 64;
    const float4* x4 = reinterpret_cast<const float4*>(x);
    const float4* a4 = reinterpret_cast<const float4*>(agg);
    float4* in4 = reinterpret_cast<float4*>(ins);
    for (int i = tid; i < 64 * K4; i += 256) {
        const int r = i / K4, c = i % K4;
        const int n = base + r;
        float4 v = make_float4(0.f, 0.f, 0.f, 0.f);
        if (n < N_NODES) {
            float4 xv = x4[(size_t)n * K4 + c];
            float4 av = a4[(size_t)n * K4 + c];
            v = make_float4(xv.x + av.x, xv.y + av.y, xv.z + av.z, xv.w + av.w);
        }
        in4[i] = v;
    }
    __syncthreads();

    const int w = tid >> 5, lane = tid & 31;
    const float4 bj = reinterpret_cast<const float4*>(b)[lane];
    u64 acc0[8], acc1[8];
    const u64 bp0 = pack2(bj.x, bj.y), bp1 = pack2(bj.z, bj.w);
#pragma unroll
    for (int m = 0; m < 8; m++) { acc0[m] = bp0; acc1[m] = bp1; }

    const float* inrow = ins + (w * 8) * K;
#pragma unroll 1
    for (int k = 0; k < K; k += 4) {
        const float4 wv0 = Ws4[(k + 0) * 32 + lane];
        const float4 wv1 = Ws4[(k + 1) * 32 + lane];
        const float4 wv2 = Ws4[(k + 2) * 32 + lane];
        const float4 wv3 = Ws4[(k + 3) * 32 + lane];
        const u64 w00 = pack2(wv0.x, wv0.y), w01 = pack2(wv0.z, wv0.w);
        const u64 w10 = pack2(wv1.x, wv1.y), w11 = pack2(wv1.z, wv1.w);
        const u64 w20 = pack2(wv2.x, wv2.y), w21 = pack2(wv2.z, wv2.w);
        const u64 w30 = pack2(wv3.x, wv3.y), w31 = pack2(wv3.z, wv3.w);
#pragma unroll
        for (int m = 0; m < 8; m++) {
            const float4 iv = *reinterpret_cast<const float4*>(inrow + m * K + k);
            u64 t;
            t = pack2(iv.x, iv.x);
            acc0[m] = fma2(t, w00, acc0[m]);
            acc1[m] = fma2(t, w01, acc1[m]);
            t = pack2(iv.y, iv.y);
            acc0[m] = fma2(t, w10, acc0[m]);
            acc1[m] = fma2(t, w11, acc1[m]);
            t = pack2(iv.z, iv.z);
            acc0[m] = fma2(t, w20, acc0[m]);
            acc1[m] = fma2(t, w21, acc1[m]);
            t = pack2(iv.w, iv.w);
            acc0[m] = fma2(t, w30, acc0[m]);
            acc1[m] = fma2(t, w31, acc1[m]);
        }
    }

#pragma unroll
    for (int m = 0; m < 8; m++) {
        const int n = base + w * 8 + m;
        if (n < N_NODES) {
            const float2 lo = unpack2(acc0[m]);
            const float2 hi = unpack2(acc1[m]);
            float4 r;
            r.x = fmaxf(lo.x, 0.f);
            r.y = fmaxf(lo.y, 0.f);
            r.z = fmaxf(hi.x, 0.f);
            r.w = fmaxf(hi.y, 0.f);
            if (POOL) {
                const int g = batch[n];
                red_add_v4(&g_sums[(size_t)g * HIDDEN + lane * 4], r);
            } else {
                reinterpret_cast<float4*>(out)[(size_t)n * 32 + lane] = r;
            }
        }
    }
}

// ---------------- per-graph node counts (smem histogram) ----------------
__global__ void count_kernel(const int* __restrict__ batch) {
    __shared__ int hist[NUM_GRAPHS];
    for (int i = threadIdx.x; i < NUM_GRAPHS; i += blockDim.x) hist[i] = 0;
    __syncthreads();
    for (int n = blockIdx.x * blockDim.x + threadIdx.x; n < N_NODES; n += gridDim.x * blockDim.x)
        atomicAdd(&hist[batch[n]], 1);
    __syncthreads();
    for (int i = threadIdx.x; i < NUM_GRAPHS; i += blockDim.x)
        if (hist[i]) atomicAdd(&g_counts[i], hist[i]);
}

// ---------------- final divide ----------------
__global__ void div_kernel(float* __restrict__ out) {
    const int g = blockIdx.x;
    const int j = threadIdx.x;
    const float c = fmaxf((float)g_counts[g], 1.0f);
    out[g * HIDDEN + j] = g_sums[g * HIDDEN + j] / c;
}

// ---------------- device-symbol address helpers (host API only; capture-safe) ----------------
template <typename T>
static T* sym_addr(T& sym) {
    void* p = nullptr;
    cudaGetSymbolAddress(&p, sym);
    return (T*)p;
}

// ---------------- launch ----------------
extern "C" void kernel_launch(void* const* d_in, const int* in_sizes, int n_in,
                              void* d_out, int out_size) {
    const float* x     = (const float*)d_in[0];
    const int*   ei    = (const int*)d_in[1];
    const float* ea    = (const float*)d_in[2];
    const int*   batch = (const int*)d_in[3];
    const float *W1 = (const float*)d_in[4],  *b1 = (const float*)d_in[5];
    const float *We1= (const float*)d_in[6],  *be1= (const float*)d_in[7];
    const float *W2 = (const float*)d_in[8],  *b2 = (const float*)d_in[9];
    const float *We2= (const float*)d_in[10], *be2= (const float*)d_in[11];
    const float *W3 = (const float*)d_in[12], *b3 = (const float*)d_in[13];
    const float *We3= (const float*)d_in[14], *be3= (const float*)d_in[15];
    float* out = (float*)d_out;

    float* agg1 = sym_addr(*g_agg1);
    float* agg2 = sym_addr(*g_agg2);
    float* agg3 = sym_addr(*g_agg3);
    float* h1   = sym_addr(*g_h1);
    float* h2   = sym_addr(*g_h2);

    const int smem64  = (64  * 128 + 64 * 64)  * 4;  // 48 KB
    const int smem128 = (128 * 128 + 64 * 128) * 4;  // 96 KB
    cudaFuncSetAttribute(node_kernel<64,  false>, cudaFuncAttributeMaxDynamicSharedMemorySize, smem64);
    cudaFuncSetAttribute(node_kernel<128, false>, cudaFuncAttributeMaxDynamicSharedMemorySize, smem128);
    cudaFuncSetAttribute(node_kernel<128, true >, cudaFuncAttributeMaxDynamicSharedMemorySize, smem128);

    const int EDGE_GRID = 152 * 8;
    const int NODE_GRID = (N_NODES + 63) / 64;

    zero_a_kernel<<<1024, 256>>>();                                                      // 1
    zero_b_kernel<<<2048, 256>>>();                                                      // 2
    edge_kernel64<<<EDGE_GRID, 256>>>(x, ei, ea, We1, be1, agg1);                        // 3
    node_kernel<64, false><<<NODE_GRID, 256, smem64>>>(x, agg1, W1, b1, nullptr, h1);    // 4
    edge_kernel128<<<EDGE_GRID, 256>>>(h1, ei, ea, We2, be2, agg2);                      // 5
    node_kernel<128, false><<<NODE_GRID, 256, smem128>>>(h1, agg2, W2, b2, nullptr, h2); // 6
    edge_kernel128<<<EDGE_GRID, 256>>>(h2, ei, ea, We3, be3, agg3);                      // 7
    zero_pool_kernel<<<32, 256>>>();                                                     // 8  (before pooled node kernel)
    count_kernel<<<128, 256>>>(batch);                                                   // 9
    node_kernel<128, true><<<NODE_GRID, 256, smem128>>>(h2, agg3, W3, b3, batch, nullptr); // 10
    div_kernel<<<NUM_GRAPHS, HIDDEN>>>(out);                                             // 11
}